// round 4
// baseline (speedup 1.0000x reference)
#include <cuda_runtime.h>
#include <cuda_bf16.h>
#include <math.h>
#include <stdint.h>

#define CC 256
#define NN 4096
#define BB 16
#define NH 8
#define HD 32
#define HH 64
#define WW 64
#define M_QKV 768
#define SEGS 8

// ---------------- scratch (device globals; no allocation allowed) ----------------
__device__ float g_qkv[(size_t)BB * M_QKV * NN];   // (B, 768, N) fp32: q | k | v
__device__ float g_mid[(size_t)BB * CC * NN];      // (B, C, N) pre-projection fp32
__device__ float g_kvp[SEGS * BB * NH * HD * HD];  // partial kv states
__device__ float g_ksp[SEGS * BB * NH * HD];       // partial ksums
__device__ float g_bcat[M_QKV];
__device__ float g_invscale[CC];
// pre-split bf16 weights (uint4-typed for 16B alignment)
__device__ uint4 g_whi4 [M_QKV * CC * 2 / 16];
__device__ uint4 g_wlo4 [M_QKV * CC * 2 / 16];
__device__ uint4 g_pwhi4[CC * CC * 2 / 16];
__device__ uint4 g_pwlo4[CC * CC * 2 / 16];

// ---------------- ptx helpers (baseline sm_80+ ISA only) ----------------
__device__ __forceinline__ uint32_t smem_u32(const void* p) {
    uint32_t a;
    asm("{ .reg .u64 t; cvta.to.shared.u64 t, %1; cvt.u32.u64 %0, t; }" : "=r"(a) : "l"(p));
    return a;
}
__device__ __forceinline__ void cp_async16(uint32_t saddr, const void* gptr) {
    asm volatile("cp.async.cg.shared.global [%0], [%1], 16;"
                 :: "r"(saddr), "l"(__cvta_generic_to_global(gptr)) : "memory");
}
__device__ __forceinline__ void ldsm_x4(uint32_t* r, uint32_t addr) {
    asm volatile("ldmatrix.sync.aligned.m8n8.x4.shared.b16 {%0,%1,%2,%3}, [%4];"
                 : "=r"(r[0]), "=r"(r[1]), "=r"(r[2]), "=r"(r[3]) : "r"(addr));
}
__device__ __forceinline__ void ldsm_x4_t(uint32_t* r, uint32_t addr) {
    asm volatile("ldmatrix.sync.aligned.m8n8.x4.trans.shared.b16 {%0,%1,%2,%3}, [%4];"
                 : "=r"(r[0]), "=r"(r[1]), "=r"(r[2]), "=r"(r[3]) : "r"(addr));
}
__device__ __forceinline__ void mma_bf16(float* c, const uint32_t* a, const uint32_t* b) {
    asm volatile(
        "mma.sync.aligned.m16n8k16.row.col.f32.bf16.bf16.f32 "
        "{%0,%1,%2,%3}, {%4,%5,%6,%7}, {%8,%9}, {%0,%1,%2,%3};"
        : "+f"(c[0]), "+f"(c[1]), "+f"(c[2]), "+f"(c[3])
        : "r"(a[0]), "r"(a[1]), "r"(a[2]), "r"(a[3]), "r"(b[0]), "r"(b[1]));
}
__device__ __forceinline__ void splitbf(float a, float b, uint32_t& hh, uint32_t& ll) {
    __nv_bfloat16 ha = __float2bfloat16(a), hb = __float2bfloat16(b);
    float ra = a - __bfloat162float(ha), rb = b - __bfloat162float(hb);
    __nv_bfloat16 la = __float2bfloat16(ra), lb = __float2bfloat16(rb);
    hh = (uint32_t)__bfloat16_as_ushort(ha) | ((uint32_t)__bfloat16_as_ushort(hb) << 16);
    ll = (uint32_t)__bfloat16_as_ushort(la) | ((uint32_t)__bfloat16_as_ushort(lb) << 16);
}

// ---------------- prep: weight hi/lo split + biases + inv softplus scale ----------------
__global__ void prep_kernel(const float* __restrict__ Wq, const float* __restrict__ bq,
                            const float* __restrict__ Wkv, const float* __restrict__ bkv,
                            const float* __restrict__ Wproj, const float* __restrict__ scale_param) {
    int r = blockIdx.x, t = threadIdx.x;
    float w = (r < CC) ? Wq[(size_t)r * CC + t] : Wkv[(size_t)(r - CC) * CC + t];
    __nv_bfloat16 h = __float2bfloat16(w);
    ((__nv_bfloat16*)g_whi4)[(size_t)r * CC + t] = h;
    ((__nv_bfloat16*)g_wlo4)[(size_t)r * CC + t] = __float2bfloat16(w - __bfloat162float(h));
    if (r < CC) {
        float pw = Wproj[(size_t)r * CC + t];
        __nv_bfloat16 ph = __float2bfloat16(pw);
        ((__nv_bfloat16*)g_pwhi4)[r * CC + t] = ph;
        ((__nv_bfloat16*)g_pwlo4)[r * CC + t] = __float2bfloat16(pw - __bfloat162float(ph));
    }
    if (t == 0) {
        g_bcat[r] = (r < CC) ? bq[r] : bkv[r - CC];
        if (r < CC) {
            float s = scale_param[r];
            float sp = (s > 20.f) ? s : log1pf(expf(s));
            g_invscale[r] = 1.0f / sp;
        }
    }
}

// ---------------- mma.sync GEMM: out[b] = A(Mx256) @ Bf32[b](256x4096) + bias ----------------
// A pre-split bf16 hi/lo; B fp32 loaded via cp.async, converted to bf16 hi/lo in smem.
// 8 k-chunks of 32; per chunk 3 MMA terms: Ah*Bh + Ah*Bl + Al*Bh.
#define STAGES 4
#define NCHUNK 8
#define A_STRIDE 80
#define ACH_BYTES (128 * A_STRIDE)        // 10240 per term per chunk
#define BF32_STRIDE 528                   // 128 floats * 4 + 16 pad
#define BF32_BYTES (32 * BF32_STRIDE)     // 16896
#define STAGE_BYTES (2 * ACH_BYTES + BF32_BYTES)  // 37376
#define B_STRIDE 272
#define BCVT_BYTES (32 * B_STRIDE)        // 8704 per term
#define SM_GEMM (STAGES * STAGE_BYTES + 2 * BCVT_BYTES)  // 166912

__global__ __launch_bounds__(256)
void gemm_mma_kernel(const __nv_bfloat16* __restrict__ Ahi, const __nv_bfloat16* __restrict__ Alo,
                     const float* __restrict__ Bsrc, const float* __restrict__ bias,
                     float* __restrict__ out, int M) {
    extern __shared__ char smem[];
    uint32_t sb = smem_u32(smem);
    int tid = threadIdx.x, lane = tid & 31, wid = tid >> 5;
    int n0 = blockIdx.x * 128, mbase = blockIdx.y * 128, bz = blockIdx.z;
    int wm = (wid & 3) * 32, wn = (wid >> 2) * 64;
    const float* Bb = Bsrc + (size_t)bz * CC * NN;
    const __nv_bfloat16* Ahm = Ahi + (size_t)mbase * CC;
    const __nv_bfloat16* Alm = Alo + (size_t)mbase * CC;

    float acc[2][8][4];
#pragma unroll
    for (int mt = 0; mt < 2; mt++)
#pragma unroll
        for (int nt = 0; nt < 8; nt++)
#pragma unroll
            for (int i = 0; i < 4; i++) acc[mt][nt][i] = 0.f;

    int r0 = (tid * 2) >> 2, kc0 = (tid * 2) & 3;
    int r1 = (tid * 2 + 1) >> 2, kc1 = (tid * 2 + 1) & 3;
    int brow = tid & 31, bcolf = (tid >> 5) * 16;

    auto issue = [&](int ck) {
        if (ck < NCHUNK) {
            int kb = ck * 32, s = ck & (STAGES - 1);
            uint32_t sA = sb + s * STAGE_BYTES;
            cp_async16(sA + r0 * A_STRIDE + kc0 * 16, Ahm + (size_t)r0 * CC + kb + kc0 * 8);
            cp_async16(sA + r1 * A_STRIDE + kc1 * 16, Ahm + (size_t)r1 * CC + kb + kc1 * 8);
            cp_async16(sA + ACH_BYTES + r0 * A_STRIDE + kc0 * 16, Alm + (size_t)r0 * CC + kb + kc0 * 8);
            cp_async16(sA + ACH_BYTES + r1 * A_STRIDE + kc1 * 16, Alm + (size_t)r1 * CC + kb + kc1 * 8);
            uint32_t dB = sA + 2 * ACH_BYTES + brow * BF32_STRIDE + bcolf * 4;
            const float* src = Bb + (size_t)(kb + brow) * NN + n0 + bcolf;
            cp_async16(dB, src);       cp_async16(dB + 16, src + 4);
            cp_async16(dB + 32, src + 8); cp_async16(dB + 48, src + 12);
        }
        asm volatile("cp.async.commit_group;" ::: "memory");
    };
    issue(0); issue(1); issue(2);

    int li = lane >> 3, lr = lane & 7;
    uint32_t sCVT = sb + STAGES * STAGE_BYTES;

    for (int ck = 0; ck < NCHUNK; ck++) {
        asm volatile("cp.async.wait_group 2;" ::: "memory");
        __syncthreads();
        issue(ck + 3);
        // convert fp32 stage -> bf16 hi/lo tiles
        {
            int s = ck & (STAGES - 1);
            const float4* sp = (const float4*)(smem + s * STAGE_BYTES + 2 * ACH_BYTES
                                               + brow * BF32_STRIDE + bcolf * 4);
            uint32_t hb[8], lb[8];
#pragma unroll
            for (int u = 0; u < 4; u++) {
                float4 v = sp[u];
                splitbf(v.x, v.y, hb[2 * u], lb[2 * u]);
                splitbf(v.z, v.w, hb[2 * u + 1], lb[2 * u + 1]);
            }
            uint4* dh = (uint4*)(smem + STAGES * STAGE_BYTES + brow * B_STRIDE + bcolf * 2);
            uint4* dl = (uint4*)(smem + STAGES * STAGE_BYTES + BCVT_BYTES + brow * B_STRIDE + bcolf * 2);
            dh[0] = make_uint4(hb[0], hb[1], hb[2], hb[3]);
            dh[1] = make_uint4(hb[4], hb[5], hb[6], hb[7]);
            dl[0] = make_uint4(lb[0], lb[1], lb[2], lb[3]);
            dl[1] = make_uint4(lb[4], lb[5], lb[6], lb[7]);
        }
        __syncthreads();

        int s = ck & (STAGES - 1);
        uint32_t sA = sb + s * STAGE_BYTES;
#pragma unroll
        for (int ks = 0; ks < 2; ks++) {
            uint32_t ah[2][4], al[2][4];
#pragma unroll
            for (int mt = 0; mt < 2; mt++) {
                uint32_t aaddr = sA + (uint32_t)(wm + mt * 16 + (li & 1) * 8 + lr) * A_STRIDE
                                    + (uint32_t)(ks * 32 + (li >> 1) * 16);
                ldsm_x4(ah[mt], aaddr);
                ldsm_x4(al[mt], aaddr + ACH_BYTES);
            }
            uint32_t bh[8][2], bl[8][2];
#pragma unroll
            for (int j = 0; j < 4; j++) {
                uint32_t baddr = sCVT + (uint32_t)(ks * 16 + (li & 1) * 8 + lr) * B_STRIDE
                                      + (uint32_t)(wn + j * 16 + (li >> 1) * 8) * 2;
                uint32_t t4[4];
                ldsm_x4_t(t4, baddr);
                bh[2 * j][0] = t4[0]; bh[2 * j][1] = t4[1];
                bh[2 * j + 1][0] = t4[2]; bh[2 * j + 1][1] = t4[3];
                ldsm_x4_t(t4, baddr + BCVT_BYTES);
                bl[2 * j][0] = t4[0]; bl[2 * j][1] = t4[1];
                bl[2 * j + 1][0] = t4[2]; bl[2 * j + 1][1] = t4[3];
            }
#pragma unroll
            for (int mt = 0; mt < 2; mt++)
#pragma unroll
                for (int nt = 0; nt < 8; nt++) {
                    mma_bf16(acc[mt][nt], ah[mt], bh[nt]);
                    mma_bf16(acc[mt][nt], ah[mt], bl[nt]);
                    mma_bf16(acc[mt][nt], al[mt], bh[nt]);
                }
        }
        __syncthreads();
    }

    // epilogue
    int g = lane >> 2, tg = lane & 3;
#pragma unroll
    for (int mt = 0; mt < 2; mt++) {
        int m = mbase + wm + mt * 16 + g;
        float bv0 = bias[m], bv1 = bias[m + 8];
        float* po0 = out + ((size_t)bz * M + m) * NN + n0 + wn + tg * 2;
        float* po1 = po0 + 8 * (size_t)NN;
#pragma unroll
        for (int nt = 0; nt < 8; nt++) {
            *(float2*)(po0 + nt * 8) = make_float2(acc[mt][nt][0] + bv0, acc[mt][nt][1] + bv0);
            *(float2*)(po1 + nt * 8) = make_float2(acc[mt][nt][2] + bv1, acc[mt][nt][3] + bv1);
        }
    }
}

// ---------------- single-pass focusing transform (q and k) ----------------
#define FOC_SMEM (256 * 65 * 4 + 256 * 4 + 256 * 4 + 256 * 4 + 64 * 4)
__global__ __launch_bounds__(256)
void focus_kernel() {
    extern __shared__ char fsm[];
    float* tile = (float*)fsm;                       // 256 x 65
    float* sinv = (float*)(fsm + 256 * 65 * 4);      // 256
    float* sp2  = sinv + 256;                        // 4 x 64
    float* sp6  = sp2 + 256;                         // 4 x 64
    float* sf   = sp6 + 256;                         // 64
    int tid = threadIdx.x;
    int part = blockIdx.y, b = blockIdx.z;
    int n0 = blockIdx.x * 64;
    sinv[tid] = g_invscale[tid];
    float* base = g_qkv + ((size_t)b * M_QKV + part * CC) * NN + n0;
    int j = tid & 63, ci = tid >> 6;
    __syncthreads();
#pragma unroll 8
    for (int i = 0; i < 64; i++) {
        int c = i * 4 + ci;
        float v = base[(size_t)c * NN + j];
        v = fmaxf(v, 0.f) + 1e-6f;
        tile[c * 65 + j] = v * sinv[c];
    }
    __syncthreads();
    float s2 = 0.f, s6 = 0.f;
#pragma unroll 8
    for (int c = ci * 64; c < ci * 64 + 64; c++) {
        float v = tile[c * 65 + j];
        float v2 = v * v, v3 = v2 * v;
        s2 += v2; s6 += v3 * v3;
        tile[c * 65 + j] = v3;
    }
    sp2[ci * 64 + j] = s2;
    sp6[ci * 64 + j] = s6;
    __syncthreads();
    if (tid < 64) {
        float t2 = sp2[tid] + sp2[64 + tid] + sp2[128 + tid] + sp2[192 + tid];
        float t6 = sp6[tid] + sp6[64 + tid] + sp6[128 + tid] + sp6[192 + tid];
        sf[tid] = sqrtf(t2 / t6);
    }
    __syncthreads();
    float f = sf[j];
#pragma unroll 8
    for (int i = 0; i < 64; i++) {
        int c = i * 4 + ci;
        base[(size_t)c * NN + j] = tile[c * 65 + j] * f;
    }
}

// ---------------- per-head kv_state partials (split over N segments) ----------------
#define CHUNK 128
__global__ __launch_bounds__(256)
void kvstate_kernel() {
    int bh = blockIdx.x, seg = blockIdx.y;
    int b = bh >> 3, h = bh & 7;
    const float* kbase = g_qkv + ((size_t)b * M_QKV + CC + h * HD) * NN;
    const float* vbase = g_qkv + ((size_t)b * M_QKV + 2 * CC + h * HD) * NN;
    __shared__ float sk[HD][CHUNK + 1];
    __shared__ float sv[HD][CHUNK + 1];
    int tid = threadIdx.x;
    int c = tid >> 3, d4 = (tid & 7) * 4;
    int lrow = tid >> 3, lcol = (tid & 7) * 16;
    float acc[4] = {0, 0, 0, 0};
    float ks = 0.f;
    int j_begin = seg * (NN / SEGS);

    for (int j0 = j_begin; j0 < j_begin + NN / SEGS; j0 += CHUNK) {
#pragma unroll
        for (int i = 0; i < 16; i += 4) {
            float4 k4 = *(const float4*)(kbase + (size_t)lrow * NN + j0 + lcol + i);
            sk[lrow][lcol + i + 0] = k4.x; sk[lrow][lcol + i + 1] = k4.y;
            sk[lrow][lcol + i + 2] = k4.z; sk[lrow][lcol + i + 3] = k4.w;
            float4 v4 = *(const float4*)(vbase + (size_t)lrow * NN + j0 + lcol + i);
            sv[lrow][lcol + i + 0] = v4.x; sv[lrow][lcol + i + 1] = v4.y;
            sv[lrow][lcol + i + 2] = v4.z; sv[lrow][lcol + i + 3] = v4.w;
        }
        __syncthreads();
        for (int j = 0; j < CHUNK; j++) {
            float kc = sk[c][j];
            ks += kc;
#pragma unroll
            for (int i = 0; i < 4; i++) acc[i] += kc * sv[d4 + i][j];
        }
        __syncthreads();
    }
    float* kvs = g_kvp + ((size_t)seg * BB * NH + bh) * HD * HD;
#pragma unroll
    for (int i = 0; i < 4; i++) kvs[c * HD + d4 + i] = acc[i];
    if ((tid & 7) == 0) g_ksp[((size_t)seg * BB * NH + bh) * HD + c] = ks;
}

// ---------------- fused depthwise conv + attention output -> g_mid (fp32) ----------------
__global__ __launch_bounds__(256)
void conv_attn_kernel(const float* __restrict__ dwc_w, const float* __restrict__ dwc_b) {
    __shared__ float skvs[HD * HD];
    __shared__ float sks[HD];
    __shared__ float tile[20][21];
    __shared__ float wloc[25];
    int bh = blockIdx.y;
    int b = bh >> 3, h = bh & 7;
    int ty0 = (blockIdx.x >> 2) * 16;
    int tx0 = (blockIdx.x & 3) * 16;
    int tid = threadIdx.x, lx = tid & 15, ly = tid >> 4;
    int gy = ty0 + ly, gx = tx0 + lx;
    int n = gy * WW + gx;

    // reduce kv_state partials into smem
    for (int i = tid; i < HD * HD; i += 256) {
        float s = 0.f;
#pragma unroll
        for (int seg = 0; seg < SEGS; seg++)
            s += g_kvp[((size_t)seg * BB * NH + bh) * HD * HD + i];
        skvs[i] = s;
    }
    if (tid < HD) {
        float s = 0.f;
#pragma unroll
        for (int seg = 0; seg < SEGS; seg++)
            s += g_ksp[((size_t)seg * BB * NH + bh) * HD + tid];
        sks[tid] = s;
    }

    // depthwise conv: per-pixel results stay in registers
    float acc[HD];
    for (int d = 0; d < HD; d++) {
        const float* vrow = g_qkv + ((size_t)b * M_QKV + 2 * CC + h * HD + d) * NN;
        __syncthreads();
        if (tid < 25) wloc[tid] = dwc_w[d * 25 + tid];
        for (int i = tid; i < 400; i += 256) {
            int ry = i / 20, rx = i % 20;
            int sy = ty0 - 2 + ry, sx = tx0 - 2 + rx;
            float v = 0.f;
            if (sy >= 0 && sy < HH && sx >= 0 && sx < WW) v = vrow[sy * WW + sx];
            tile[ry][rx] = v;
        }
        __syncthreads();
        float a = dwc_b[d];
#pragma unroll
        for (int ky = 0; ky < 5; ky++)
#pragma unroll
            for (int kx = 0; kx < 5; kx++)
                a += tile[ly + ky][lx + kx] * wloc[ky * 5 + kx];
        acc[d] = a;
    }
    __syncthreads();

    // attention: out = conv + z * (kvs^T q)
    const float* qbase = g_qkv + ((size_t)b * M_QKV + h * HD) * NN + n;
    float a2[HD];
#pragma unroll
    for (int d = 0; d < HD; d++) a2[d] = 0.f;
    float zacc = 0.f;
#pragma unroll
    for (int c = 0; c < HD; c++) {
        float qv = qbase[(size_t)c * NN];
        zacc += qv * sks[c];
#pragma unroll
        for (int d = 0; d < HD; d++) a2[d] += qv * skvs[c * HD + d];
    }
    float z = 1.0f / (zacc + 1e-6f);
#pragma unroll
    for (int d = 0; d < HD; d++)
        g_mid[((size_t)b * CC + h * HD + d) * NN + n] = acc[d] + a2[d] * z;
}

// ---------------- launch ----------------
extern "C" void kernel_launch(void* const* d_in, const int* in_sizes, int n_in,
                              void* d_out, int out_size) {
    const float* x           = (const float*)d_in[0];
    const float* Wq          = (const float*)d_in[1];
    const float* bq          = (const float*)d_in[2];
    const float* Wkv         = (const float*)d_in[3];
    const float* bkv         = (const float*)d_in[4];
    const float* Wproj       = (const float*)d_in[5];
    const float* bproj       = (const float*)d_in[6];
    const float* dwc_w       = (const float*)d_in[7];
    const float* dwc_b       = (const float*)d_in[8];
    const float* scale_param = (const float*)d_in[9];
    float* out = (float*)d_out;

    float *p_qkv, *p_mid, *p_bcat;
    uint4 *p_whi, *p_wlo, *p_pwhi, *p_pwlo;
    cudaGetSymbolAddress((void**)&p_qkv,  g_qkv);
    cudaGetSymbolAddress((void**)&p_mid,  g_mid);
    cudaGetSymbolAddress((void**)&p_bcat, g_bcat);
    cudaGetSymbolAddress((void**)&p_whi,  g_whi4);
    cudaGetSymbolAddress((void**)&p_wlo,  g_wlo4);
    cudaGetSymbolAddress((void**)&p_pwhi, g_pwhi4);
    cudaGetSymbolAddress((void**)&p_pwlo, g_pwlo4);

    cudaFuncSetAttribute(gemm_mma_kernel, cudaFuncAttributeMaxDynamicSharedMemorySize, SM_GEMM);
    cudaFuncSetAttribute(focus_kernel, cudaFuncAttributeMaxDynamicSharedMemorySize, FOC_SMEM);

    prep_kernel<<<M_QKV, CC>>>(Wq, bq, Wkv, bkv, Wproj, scale_param);

    // QKV projection: 768x256 @ 256x4096 per batch (B = x fp32, converted inline)
    gemm_mma_kernel<<<dim3(NN / 128, M_QKV / 128, BB), 256, SM_GEMM>>>(
        (const __nv_bfloat16*)p_whi, (const __nv_bfloat16*)p_wlo,
        x, p_bcat, p_qkv, M_QKV);

    focus_kernel<<<dim3(NN / 64, 2, BB), 256, FOC_SMEM>>>();

    kvstate_kernel<<<dim3(BB * NH, SEGS), 256>>>();

    conv_attn_kernel<<<dim3(16, BB * NH), 256>>>(dwc_w, dwc_b);

    // Output projection: 256x256 @ 256x4096 per batch (B = g_mid fp32, converted inline)
    gemm_mma_kernel<<<dim3(NN / 128, CC / 128, BB), 256, SM_GEMM>>>(
        (const __nv_bfloat16*)p_pwhi, (const __nv_bfloat16*)p_pwlo,
        p_mid, bproj, out, CC);
}

// round 5
// speedup vs baseline: 1.1579x; 1.1579x over previous
#include <cuda_runtime.h>
#include <cuda_bf16.h>
#include <math.h>
#include <stdint.h>

#define CC 256
#define NN 4096
#define BB 16
#define NH 8
#define HD 32
#define HH 64
#define WW 64
#define M_QKV 768
#define SEGS 8

// ---------------- scratch (device globals; no allocation allowed) ----------------
__device__ float g_qkv[(size_t)BB * M_QKV * NN];   // (B, 768, N) fp32: q | k | v
__device__ float g_kvp[SEGS * BB * NH * HD * HD];  // partial kv states
__device__ float g_ksp[SEGS * BB * NH * HD];       // partial ksums
__device__ float g_bcat[M_QKV];
__device__ float g_invscale[CC];
// bf16 hi/lo buffers (uint4-typed for 16B alignment)
__device__ uint4 g_whi4 [M_QKV * CC * 2 / 16];
__device__ uint4 g_wlo4 [M_QKV * CC * 2 / 16];
__device__ uint4 g_pwhi4[CC * CC * 2 / 16];
__device__ uint4 g_pwlo4[CC * CC * 2 / 16];
__device__ uint4 g_xhi4 [(size_t)BB * CC * NN * 2 / 16];
__device__ uint4 g_xlo4 [(size_t)BB * CC * NN * 2 / 16];
__device__ uint4 g_mhi4 [(size_t)BB * CC * NN * 2 / 16];
__device__ uint4 g_mlo4 [(size_t)BB * CC * NN * 2 / 16];

// ---------------- ptx helpers (baseline sm_80+ ISA only) ----------------
__device__ __forceinline__ uint32_t smem_u32(const void* p) {
    uint32_t a;
    asm("{ .reg .u64 t; cvta.to.shared.u64 t, %1; cvt.u32.u64 %0, t; }" : "=r"(a) : "l"(p));
    return a;
}
__device__ __forceinline__ void cp_async16(uint32_t saddr, const void* gptr) {
    asm volatile("cp.async.cg.shared.global [%0], [%1], 16;"
                 :: "r"(saddr), "l"(__cvta_generic_to_global(gptr)) : "memory");
}
__device__ __forceinline__ void ldsm_x4(uint32_t* r, uint32_t addr) {
    asm volatile("ldmatrix.sync.aligned.m8n8.x4.shared.b16 {%0,%1,%2,%3}, [%4];"
                 : "=r"(r[0]), "=r"(r[1]), "=r"(r[2]), "=r"(r[3]) : "r"(addr));
}
__device__ __forceinline__ void ldsm_x4_t(uint32_t* r, uint32_t addr) {
    asm volatile("ldmatrix.sync.aligned.m8n8.x4.trans.shared.b16 {%0,%1,%2,%3}, [%4];"
                 : "=r"(r[0]), "=r"(r[1]), "=r"(r[2]), "=r"(r[3]) : "r"(addr));
}
__device__ __forceinline__ void mma_bf16(float* c, const uint32_t* a, const uint32_t* b) {
    asm volatile(
        "mma.sync.aligned.m16n8k16.row.col.f32.bf16.bf16.f32 "
        "{%0,%1,%2,%3}, {%4,%5,%6,%7}, {%8,%9}, {%0,%1,%2,%3};"
        : "+f"(c[0]), "+f"(c[1]), "+f"(c[2]), "+f"(c[3])
        : "r"(a[0]), "r"(a[1]), "r"(a[2]), "r"(a[3]), "r"(b[0]), "r"(b[1]));
}

// ---------------- prep: weight hi/lo split + biases + inv softplus scale ----------------
__global__ void prep_kernel(const float* __restrict__ Wq, const float* __restrict__ bq,
                            const float* __restrict__ Wkv, const float* __restrict__ bkv,
                            const float* __restrict__ Wproj, const float* __restrict__ scale_param) {
    int r = blockIdx.x, t = threadIdx.x;
    float w = (r < CC) ? Wq[(size_t)r * CC + t] : Wkv[(size_t)(r - CC) * CC + t];
    __nv_bfloat16 h = __float2bfloat16(w);
    ((__nv_bfloat16*)g_whi4)[(size_t)r * CC + t] = h;
    ((__nv_bfloat16*)g_wlo4)[(size_t)r * CC + t] = __float2bfloat16(w - __bfloat162float(h));
    if (r < CC) {
        float pw = Wproj[(size_t)r * CC + t];
        __nv_bfloat16 ph = __float2bfloat16(pw);
        ((__nv_bfloat16*)g_pwhi4)[r * CC + t] = ph;
        ((__nv_bfloat16*)g_pwlo4)[r * CC + t] = __float2bfloat16(pw - __bfloat162float(ph));
    }
    if (t == 0) {
        g_bcat[r] = (r < CC) ? bq[r] : bkv[r - CC];
        if (r < CC) {
            float s = scale_param[r];
            float sp = (s > 20.f) ? s : log1pf(expf(s));
            g_invscale[r] = 1.0f / sp;
        }
    }
}

// ---------------- split fp32 into bf16 hi/lo ----------------
__global__ __launch_bounds__(256)
void split_kernel(const float4* __restrict__ src, __nv_bfloat16* __restrict__ hi,
                  __nv_bfloat16* __restrict__ lo, int n4) {
    int i = blockIdx.x * 256 + threadIdx.x;
    if (i >= n4) return;
    float4 v = src[i];
    __nv_bfloat16 h0 = __float2bfloat16(v.x), h1 = __float2bfloat16(v.y);
    __nv_bfloat16 h2 = __float2bfloat16(v.z), h3 = __float2bfloat16(v.w);
    __nv_bfloat16 l0 = __float2bfloat16(v.x - __bfloat162float(h0));
    __nv_bfloat16 l1 = __float2bfloat16(v.y - __bfloat162float(h1));
    __nv_bfloat16 l2 = __float2bfloat16(v.z - __bfloat162float(h2));
    __nv_bfloat16 l3 = __float2bfloat16(v.w - __bfloat162float(h3));
    __nv_bfloat162* hp = (__nv_bfloat162*)(hi + 4 * (size_t)i);
    __nv_bfloat162* lp = (__nv_bfloat162*)(lo + 4 * (size_t)i);
    hp[0] = __halves2bfloat162(h0, h1);
    hp[1] = __halves2bfloat162(h2, h3);
    lp[0] = __halves2bfloat162(l0, l1);
    lp[1] = __halves2bfloat162(l2, l3);
}

// ---------------- mma.sync GEMM (round-3 structure): out[b] = A(Mx256) @ B[b](256x4096) + bias
// 3-term bf16 hi/lo split as virtual K = 768. CTA tile 128x128, 8 warps of 32x64.
#define STAGES 4
#define A_STRIDE 80
#define B_STRIDE 272
#define A_BYTES (128 * A_STRIDE)          // 10240
#define B_TILE_BYTES (32 * B_STRIDE)      // 8704
#define STAGE_BYTES (A_BYTES + B_TILE_BYTES)
#define NCHUNKS 24

__global__ __launch_bounds__(256)
void gemm_mma_kernel(const __nv_bfloat16* __restrict__ Ahi, const __nv_bfloat16* __restrict__ Alo,
                     const __nv_bfloat16* __restrict__ Bhi, const __nv_bfloat16* __restrict__ Blo,
                     const float* __restrict__ bias, float* __restrict__ out, int M) {
    extern __shared__ char smem[];
    uint32_t sb = smem_u32(smem);
    int tid = threadIdx.x, lane = tid & 31, wid = tid >> 5;
    int n0 = blockIdx.x * 128;
    int mbase = blockIdx.y * 128;
    int bz = blockIdx.z;
    int wm = (wid & 3) * 32;
    int wn = (wid >> 2) * 64;

    const __nv_bfloat16* Bhi_b = Bhi + (size_t)bz * CC * NN;
    const __nv_bfloat16* Blo_b = Blo + (size_t)bz * CC * NN;

    float acc[2][8][4];
#pragma unroll
    for (int mt = 0; mt < 2; mt++)
#pragma unroll
        for (int nt = 0; nt < 8; nt++)
#pragma unroll
            for (int i = 0; i < 4; i++) acc[mt][nt][i] = 0.f;

    int a_row0 = (tid * 2) >> 2, a_kc0 = (tid * 2) & 3;
    int a_row1 = (tid * 2 + 1) >> 2, a_kc1 = (tid * 2 + 1) & 3;
    int b_row0 = (tid * 2) >> 4, b_nc0 = (tid * 2) & 15;
    int b_row1 = (tid * 2 + 1) >> 4, b_nc1 = (tid * 2 + 1) & 15;

    auto issue_load = [&](int ck) {
        if (ck < NCHUNKS) {
            int term = ck >> 3;
            int kb = (ck & 7) * 32;
            const __nv_bfloat16* As = (term == 2) ? Alo : Ahi;
            const __nv_bfloat16* Bs = (term == 1) ? Blo_b : Bhi_b;
            int s = ck & (STAGES - 1);
            uint32_t sA = sb + s * STAGE_BYTES;
            uint32_t sB = sA + A_BYTES;
            cp_async16(sA + a_row0 * A_STRIDE + a_kc0 * 16,
                       As + (size_t)(mbase + a_row0) * CC + kb + a_kc0 * 8);
            cp_async16(sA + a_row1 * A_STRIDE + a_kc1 * 16,
                       As + (size_t)(mbase + a_row1) * CC + kb + a_kc1 * 8);
            cp_async16(sB + b_row0 * B_STRIDE + b_nc0 * 16,
                       Bs + (size_t)(kb + b_row0) * NN + n0 + b_nc0 * 8);
            cp_async16(sB + b_row1 * B_STRIDE + b_nc1 * 16,
                       Bs + (size_t)(kb + b_row1) * NN + n0 + b_nc1 * 8);
        }
        asm volatile("cp.async.commit_group;" ::: "memory");
    };

    issue_load(0);
    issue_load(1);
    issue_load(2);

    int li = lane >> 3, lr = lane & 7;

    for (int ck = 0; ck < NCHUNKS; ck++) {
        asm volatile("cp.async.wait_group 2;" ::: "memory");
        __syncthreads();
        issue_load(ck + 3);

        int s = ck & (STAGES - 1);
        uint32_t sA = sb + s * STAGE_BYTES;
        uint32_t sB = sA + A_BYTES;
#pragma unroll
        for (int ks = 0; ks < 2; ks++) {
            uint32_t af[2][4];
#pragma unroll
            for (int mt = 0; mt < 2; mt++) {
                uint32_t addr = sA + (uint32_t)(wm + mt * 16 + (li & 1) * 8 + lr) * A_STRIDE
                                   + (uint32_t)(ks * 32 + (li >> 1) * 16);
                ldsm_x4(af[mt], addr);
            }
            uint32_t bf[8][2];
#pragma unroll
            for (int j = 0; j < 4; j++) {
                uint32_t addr = sB + (uint32_t)(ks * 16 + (li & 1) * 8 + lr) * B_STRIDE
                                   + (uint32_t)(wn + j * 16 + (li >> 1) * 8) * 2;
                uint32_t t4[4];
                ldsm_x4_t(t4, addr);
                bf[2 * j][0] = t4[0]; bf[2 * j][1] = t4[1];
                bf[2 * j + 1][0] = t4[2]; bf[2 * j + 1][1] = t4[3];
            }
#pragma unroll
            for (int mt = 0; mt < 2; mt++)
#pragma unroll
                for (int nt = 0; nt < 8; nt++)
                    mma_bf16(acc[mt][nt], af[mt], bf[nt]);
        }
        __syncthreads();
    }

    int g = lane >> 2, tg = lane & 3;
#pragma unroll
    for (int mt = 0; mt < 2; mt++) {
        int m = mbase + wm + mt * 16 + g;
        float bv0 = bias[m], bv1 = bias[m + 8];
        float* po0 = out + ((size_t)bz * M + m) * NN + n0 + wn + tg * 2;
        float* po1 = po0 + 8 * (size_t)NN;
#pragma unroll
        for (int nt = 0; nt < 8; nt++) {
            *(float2*)(po0 + nt * 8) = make_float2(acc[mt][nt][0] + bv0, acc[mt][nt][1] + bv0);
            *(float2*)(po1 + nt * 8) = make_float2(acc[mt][nt][2] + bv1, acc[mt][nt][3] + bv1);
        }
    }
}

// ---------------- single-pass focusing transform (q and k) ----------------
#define FOC_SMEM (256 * 65 * 4 + 256 * 4 + 256 * 4 + 256 * 4 + 64 * 4)
__global__ __launch_bounds__(256)
void focus_kernel() {
    extern __shared__ char fsm[];
    float* tile = (float*)fsm;                       // 256 x 65
    float* sinv = (float*)(fsm + 256 * 65 * 4);      // 256
    float* sp2  = sinv + 256;                        // 4 x 64
    float* sp6  = sp2 + 256;                         // 4 x 64
    float* sf   = sp6 + 256;                         // 64
    int tid = threadIdx.x;
    int part = blockIdx.y, b = blockIdx.z;
    int n0 = blockIdx.x * 64;
    sinv[tid] = g_invscale[tid];
    float* base = g_qkv + ((size_t)b * M_QKV + part * CC) * NN + n0;
    int j = tid & 63, ci = tid >> 6;
    __syncthreads();
#pragma unroll 8
    for (int i = 0; i < 64; i++) {
        int c = i * 4 + ci;
        float v = base[(size_t)c * NN + j];
        v = fmaxf(v, 0.f) + 1e-6f;
        tile[c * 65 + j] = v * sinv[c];
    }
    __syncthreads();
    float s2 = 0.f, s6 = 0.f;
#pragma unroll 8
    for (int c = ci * 64; c < ci * 64 + 64; c++) {
        float v = tile[c * 65 + j];
        float v2 = v * v, v3 = v2 * v;
        s2 += v2; s6 += v3 * v3;
        tile[c * 65 + j] = v3;
    }
    sp2[ci * 64 + j] = s2;
    sp6[ci * 64 + j] = s6;
    __syncthreads();
    if (tid < 64) {
        float t2 = sp2[tid] + sp2[64 + tid] + sp2[128 + tid] + sp2[192 + tid];
        float t6 = sp6[tid] + sp6[64 + tid] + sp6[128 + tid] + sp6[192 + tid];
        sf[tid] = sqrtf(t2 / t6);
    }
    __syncthreads();
    float f = sf[j];
#pragma unroll 8
    for (int i = 0; i < 64; i++) {
        int c = i * 4 + ci;
        base[(size_t)c * NN + j] = tile[c * 65 + j] * f;
    }
}

// ---------------- per-head kv_state partials: j-major smem, float4 inner loads ----------------
#define CHUNK 128
#define JSTR 36
__global__ __launch_bounds__(256)
void kvstate_kernel() {
    int bh = blockIdx.x, seg = blockIdx.y;
    int b = bh >> 3, h = bh & 7;
    const float* kbase = g_qkv + ((size_t)b * M_QKV + CC + h * HD) * NN;
    const float* vbase = g_qkv + ((size_t)b * M_QKV + 2 * CC + h * HD) * NN;
    __shared__ __align__(16) float sk[CHUNK * JSTR];
    __shared__ __align__(16) float sv[CHUNK * JSTR];
    int tid = threadIdx.x;
    int c = tid >> 3, d4 = (tid & 7) * 4;
    int lc = tid >> 3, lj4 = (tid & 7) * 4;     // loader: row lc, 4 consecutive j
    float acc[4] = {0, 0, 0, 0};
    float ks = 0.f;
    int j_begin = seg * (NN / SEGS);

    for (int j0 = j_begin; j0 < j_begin + NN / SEGS; j0 += CHUNK) {
        // load k,v (coalesced rows) -> j-major smem (transposed scatter)
#pragma unroll
        for (int jj = 0; jj < CHUNK; jj += 32) {
            float4 k4 = *(const float4*)(kbase + (size_t)lc * NN + j0 + jj + lj4);
            float4 v4 = *(const float4*)(vbase + (size_t)lc * NN + j0 + jj + lj4);
            sk[(jj + lj4 + 0) * JSTR + lc] = k4.x;
            sk[(jj + lj4 + 1) * JSTR + lc] = k4.y;
            sk[(jj + lj4 + 2) * JSTR + lc] = k4.z;
            sk[(jj + lj4 + 3) * JSTR + lc] = k4.w;
            sv[(jj + lj4 + 0) * JSTR + lc] = v4.x;
            sv[(jj + lj4 + 1) * JSTR + lc] = v4.y;
            sv[(jj + lj4 + 2) * JSTR + lc] = v4.z;
            sv[(jj + lj4 + 3) * JSTR + lc] = v4.w;
        }
        __syncthreads();
#pragma unroll 4
        for (int j = 0; j < CHUNK; j++) {
            float kc = sk[j * JSTR + c];
            ks += kc;
            float4 v = *(const float4*)(sv + j * JSTR + d4);
            acc[0] += kc * v.x;
            acc[1] += kc * v.y;
            acc[2] += kc * v.z;
            acc[3] += kc * v.w;
        }
        __syncthreads();
    }
    float* kvs = g_kvp + ((size_t)seg * BB * NH + bh) * HD * HD;
#pragma unroll
    for (int i = 0; i < 4; i++) kvs[c * HD + d4 + i] = acc[i];
    if ((tid & 7) == 0) g_ksp[((size_t)seg * BB * NH + bh) * HD + c] = ks;
}

// ---------------- fused depthwise conv + attention output -> bf16 hi/lo mid ----------------
__global__ __launch_bounds__(256)
void conv_attn_kernel(const float* __restrict__ dwc_w, const float* __restrict__ dwc_b) {
    __shared__ float skvs[HD * HD];
    __shared__ float sks[HD];
    __shared__ float tile[20][21];
    __shared__ float wloc[25];
    int bh = blockIdx.y;
    int b = bh >> 3, h = bh & 7;
    int ty0 = (blockIdx.x >> 2) * 16;
    int tx0 = (blockIdx.x & 3) * 16;
    int tid = threadIdx.x, lx = tid & 15, ly = tid >> 4;
    int gy = ty0 + ly, gx = tx0 + lx;
    int n = gy * WW + gx;

    for (int i = tid; i < HD * HD; i += 256) {
        float s = 0.f;
#pragma unroll
        for (int seg = 0; seg < SEGS; seg++)
            s += g_kvp[((size_t)seg * BB * NH + bh) * HD * HD + i];
        skvs[i] = s;
    }
    if (tid < HD) {
        float s = 0.f;
#pragma unroll
        for (int seg = 0; seg < SEGS; seg++)
            s += g_ksp[((size_t)seg * BB * NH + bh) * HD + tid];
        sks[tid] = s;
    }

    float acc[HD];
    for (int d = 0; d < HD; d++) {
        const float* vrow = g_qkv + ((size_t)b * M_QKV + 2 * CC + h * HD + d) * NN;
        __syncthreads();
        if (tid < 25) wloc[tid] = dwc_w[d * 25 + tid];
        for (int i = tid; i < 400; i += 256) {
            int ry = i / 20, rx = i % 20;
            int sy = ty0 - 2 + ry, sx = tx0 - 2 + rx;
            float v = 0.f;
            if (sy >= 0 && sy < HH && sx >= 0 && sx < WW) v = vrow[sy * WW + sx];
            tile[ry][rx] = v;
        }
        __syncthreads();
        float a = dwc_b[d];
#pragma unroll
        for (int ky = 0; ky < 5; ky++)
#pragma unroll
            for (int kx = 0; kx < 5; kx++)
                a += tile[ly + ky][lx + kx] * wloc[ky * 5 + kx];
        acc[d] = a;
    }
    __syncthreads();

    const float* qbase = g_qkv + ((size_t)b * M_QKV + h * HD) * NN + n;
    float a2[HD];
#pragma unroll
    for (int d = 0; d < HD; d++) a2[d] = 0.f;
    float zacc = 0.f;
#pragma unroll
    for (int c = 0; c < HD; c++) {
        float qv = qbase[(size_t)c * NN];
        zacc += qv * sks[c];
#pragma unroll
        for (int d = 0; d < HD; d++) a2[d] += qv * skvs[c * HD + d];
    }
    float z = 1.0f / (zacc + 1e-6f);
    __nv_bfloat16* mh = (__nv_bfloat16*)g_mhi4;
    __nv_bfloat16* ml = (__nv_bfloat16*)g_mlo4;
#pragma unroll
    for (int d = 0; d < HD; d++) {
        size_t off = ((size_t)b * CC + h * HD + d) * NN + n;
        float v = acc[d] + a2[d] * z;
        __nv_bfloat16 hh = __float2bfloat16(v);
        mh[off] = hh;
        ml[off] = __float2bfloat16(v - __bfloat162float(hh));
    }
}

// ---------------- launch ----------------
extern "C" void kernel_launch(void* const* d_in, const int* in_sizes, int n_in,
                              void* d_out, int out_size) {
    const float* x           = (const float*)d_in[0];
    const float* Wq          = (const float*)d_in[1];
    const float* bq          = (const float*)d_in[2];
    const float* Wkv         = (const float*)d_in[3];
    const float* bkv         = (const float*)d_in[4];
    const float* Wproj       = (const float*)d_in[5];
    const float* bproj       = (const float*)d_in[6];
    const float* dwc_w       = (const float*)d_in[7];
    const float* dwc_b       = (const float*)d_in[8];
    const float* scale_param = (const float*)d_in[9];
    float* out = (float*)d_out;

    float *p_qkv, *p_bcat;
    uint4 *p_whi, *p_wlo, *p_pwhi, *p_pwlo, *p_xhi, *p_xlo, *p_mhi, *p_mlo;
    cudaGetSymbolAddress((void**)&p_qkv,  g_qkv);
    cudaGetSymbolAddress((void**)&p_bcat, g_bcat);
    cudaGetSymbolAddress((void**)&p_whi,  g_whi4);
    cudaGetSymbolAddress((void**)&p_wlo,  g_wlo4);
    cudaGetSymbolAddress((void**)&p_pwhi, g_pwhi4);
    cudaGetSymbolAddress((void**)&p_pwlo, g_pwlo4);
    cudaGetSymbolAddress((void**)&p_xhi,  g_xhi4);
    cudaGetSymbolAddress((void**)&p_xlo,  g_xlo4);
    cudaGetSymbolAddress((void**)&p_mhi,  g_mhi4);
    cudaGetSymbolAddress((void**)&p_mlo,  g_mlo4);

    int smem_gemm = STAGES * STAGE_BYTES;
    cudaFuncSetAttribute(gemm_mma_kernel, cudaFuncAttributeMaxDynamicSharedMemorySize, smem_gemm);
    cudaFuncSetAttribute(focus_kernel, cudaFuncAttributeMaxDynamicSharedMemorySize, FOC_SMEM);

    prep_kernel<<<M_QKV, CC>>>(Wq, bq, Wkv, bkv, Wproj, scale_param);

    int n4 = BB * CC * NN / 4;
    split_kernel<<<(n4 + 255) / 256, 256>>>((const float4*)x,
                                            (__nv_bfloat16*)p_xhi, (__nv_bfloat16*)p_xlo, n4);

    // QKV projection: 768x256 @ 256x4096 per batch
    gemm_mma_kernel<<<dim3(NN / 128, M_QKV / 128, BB), 256, smem_gemm>>>(
        (const __nv_bfloat16*)p_whi, (const __nv_bfloat16*)p_wlo,
        (const __nv_bfloat16*)p_xhi, (const __nv_bfloat16*)p_xlo,
        p_bcat, p_qkv, M_QKV);

    focus_kernel<<<dim3(NN / 64, 2, BB), 256, FOC_SMEM>>>();

    kvstate_kernel<<<dim3(BB * NH, SEGS), 256>>>();

    conv_attn_kernel<<<dim3(16, BB * NH), 256>>>(dwc_w, dwc_b);

    // Output projection: 256x256 @ 256x4096 per batch -> d_out
    gemm_mma_kernel<<<dim3(NN / 128, CC / 128, BB), 256, smem_gemm>>>(
        (const __nv_bfloat16*)p_pwhi, (const __nv_bfloat16*)p_pwlo,
        (const __nv_bfloat16*)p_mhi, (const __nv_bfloat16*)p_mlo,
        bproj, out, CC);
}

// round 6
// speedup vs baseline: 1.2723x; 1.0988x over previous
#include <cuda_runtime.h>
#include <cuda_bf16.h>
#include <math.h>
#include <stdint.h>

#define CC 256
#define NN 4096
#define BB 16
#define NH 8
#define HD 32
#define HH 64
#define WW 64
#define M_QKV 768
#define SEGS 8

// ---------------- scratch (device globals; no allocation allowed) ----------------
__device__ float g_qkv[(size_t)BB * M_QKV * NN];   // (B, 768, N) fp32: q | k | v
__device__ float g_kvp[SEGS * BB * NH * HD * HD];  // partial kv states
__device__ float g_ksp[SEGS * BB * NH * HD];       // partial ksums
__device__ float g_bcat[M_QKV];
__device__ float g_invscale[CC];
// bf16 hi/lo buffers (uint4-typed for 16B alignment)
__device__ uint4 g_whi4 [M_QKV * CC * 2 / 16];
__device__ uint4 g_wlo4 [M_QKV * CC * 2 / 16];
__device__ uint4 g_pwhi4[CC * CC * 2 / 16];
__device__ uint4 g_pwlo4[CC * CC * 2 / 16];
__device__ uint4 g_xhi4 [(size_t)BB * CC * NN * 2 / 16];
__device__ uint4 g_xlo4 [(size_t)BB * CC * NN * 2 / 16];
__device__ uint4 g_mhi4 [(size_t)BB * CC * NN * 2 / 16];
__device__ uint4 g_mlo4 [(size_t)BB * CC * NN * 2 / 16];

// ---------------- ptx helpers (baseline sm_80+ ISA only) ----------------
__device__ __forceinline__ uint32_t smem_u32(const void* p) {
    uint32_t a;
    asm("{ .reg .u64 t; cvta.to.shared.u64 t, %1; cvt.u32.u64 %0, t; }" : "=r"(a) : "l"(p));
    return a;
}
__device__ __forceinline__ void cp_async16(uint32_t saddr, const void* gptr) {
    asm volatile("cp.async.cg.shared.global [%0], [%1], 16;"
                 :: "r"(saddr), "l"(__cvta_generic_to_global(gptr)) : "memory");
}
__device__ __forceinline__ void ldsm_x4(uint32_t* r, uint32_t addr) {
    asm volatile("ldmatrix.sync.aligned.m8n8.x4.shared.b16 {%0,%1,%2,%3}, [%4];"
                 : "=r"(r[0]), "=r"(r[1]), "=r"(r[2]), "=r"(r[3]) : "r"(addr));
}
__device__ __forceinline__ void ldsm_x4_t(uint32_t* r, uint32_t addr) {
    asm volatile("ldmatrix.sync.aligned.m8n8.x4.trans.shared.b16 {%0,%1,%2,%3}, [%4];"
                 : "=r"(r[0]), "=r"(r[1]), "=r"(r[2]), "=r"(r[3]) : "r"(addr));
}
__device__ __forceinline__ void mma_bf16(float* c, const uint32_t* a, uint32_t b0, uint32_t b1) {
    asm volatile(
        "mma.sync.aligned.m16n8k16.row.col.f32.bf16.bf16.f32 "
        "{%0,%1,%2,%3}, {%4,%5,%6,%7}, {%8,%9}, {%0,%1,%2,%3};"
        : "+f"(c[0]), "+f"(c[1]), "+f"(c[2]), "+f"(c[3])
        : "r"(a[0]), "r"(a[1]), "r"(a[2]), "r"(a[3]), "r"(b0), "r"(b1));
}

// ---------------- prep: weight hi/lo split + biases + inv softplus scale ----------------
__global__ void prep_kernel(const float* __restrict__ Wq, const float* __restrict__ bq,
                            const float* __restrict__ Wkv, const float* __restrict__ bkv,
                            const float* __restrict__ Wproj, const float* __restrict__ scale_param) {
    int r = blockIdx.x, t = threadIdx.x;
    float w = (r < CC) ? Wq[(size_t)r * CC + t] : Wkv[(size_t)(r - CC) * CC + t];
    __nv_bfloat16 h = __float2bfloat16(w);
    ((__nv_bfloat16*)g_whi4)[(size_t)r * CC + t] = h;
    ((__nv_bfloat16*)g_wlo4)[(size_t)r * CC + t] = __float2bfloat16(w - __bfloat162float(h));
    if (r < CC) {
        float pw = Wproj[(size_t)r * CC + t];
        __nv_bfloat16 ph = __float2bfloat16(pw);
        ((__nv_bfloat16*)g_pwhi4)[r * CC + t] = ph;
        ((__nv_bfloat16*)g_pwlo4)[r * CC + t] = __float2bfloat16(pw - __bfloat162float(ph));
    }
    if (t == 0) {
        g_bcat[r] = (r < CC) ? bq[r] : bkv[r - CC];
        if (r < CC) {
            float s = scale_param[r];
            float sp = (s > 20.f) ? s : log1pf(expf(s));
            g_invscale[r] = 1.0f / sp;
        }
    }
}

// ---------------- split fp32 into bf16 hi/lo ----------------
__global__ __launch_bounds__(256)
void split_kernel(const float4* __restrict__ src, __nv_bfloat16* __restrict__ hi,
                  __nv_bfloat16* __restrict__ lo, int n4) {
    int i = blockIdx.x * 256 + threadIdx.x;
    if (i >= n4) return;
    float4 v = src[i];
    __nv_bfloat16 h0 = __float2bfloat16(v.x), h1 = __float2bfloat16(v.y);
    __nv_bfloat16 h2 = __float2bfloat16(v.z), h3 = __float2bfloat16(v.w);
    __nv_bfloat16 l0 = __float2bfloat16(v.x - __bfloat162float(h0));
    __nv_bfloat16 l1 = __float2bfloat16(v.y - __bfloat162float(h1));
    __nv_bfloat16 l2 = __float2bfloat16(v.z - __bfloat162float(h2));
    __nv_bfloat16 l3 = __float2bfloat16(v.w - __bfloat162float(h3));
    __nv_bfloat162* hp = (__nv_bfloat162*)(hi + 4 * (size_t)i);
    __nv_bfloat162* lp = (__nv_bfloat162*)(lo + 4 * (size_t)i);
    hp[0] = __halves2bfloat162(h0, h1);
    hp[1] = __halves2bfloat162(h2, h3);
    lp[0] = __halves2bfloat162(l0, l1);
    lp[1] = __halves2bfloat162(l2, l3);
}

// ---------------- mma.sync GEMM: out[b] = A(Mx256) @ B[b](256x4096) + bias ----------------
// 8 k-chunks of 32; per chunk load Ah,Al,Bh,Bl tiles ONCE, issue 3 MMA terms
// (Ah*Bh + Ah*Bl + Al*Bh) with fragment reuse. CTA 128x128, 8 warps of 32x64, 3-stage ring.
#define STAGES 3
#define NCHUNK 8
#define A_STRIDE 80
#define B_STRIDE 272
#define A_TILE 10240
#define B_TILE 8704
#define ST_AH 0
#define ST_AL (A_TILE)
#define ST_BH (2 * A_TILE)
#define ST_BL (2 * A_TILE + B_TILE)
#define STAGE_BYTES (2 * A_TILE + 2 * B_TILE)   // 37888
#define SM_GEMM (STAGES * STAGE_BYTES)          // 113664

__global__ __launch_bounds__(256)
void gemm_mma_kernel(const __nv_bfloat16* __restrict__ Ahi, const __nv_bfloat16* __restrict__ Alo,
                     const __nv_bfloat16* __restrict__ Bhi, const __nv_bfloat16* __restrict__ Blo,
                     const float* __restrict__ bias, float* __restrict__ out, int M) {
    extern __shared__ char smem[];
    uint32_t sb = smem_u32(smem);
    int tid = threadIdx.x, lane = tid & 31, wid = tid >> 5;
    int n0 = blockIdx.x * 128;
    int mbase = blockIdx.y * 128;
    int bz = blockIdx.z;
    int wm = (wid & 3) * 32;
    int wn = (wid >> 2) * 64;

    const __nv_bfloat16* Ahm = Ahi + (size_t)mbase * CC;
    const __nv_bfloat16* Alm = Alo + (size_t)mbase * CC;
    const __nv_bfloat16* Bhb = Bhi + (size_t)bz * CC * NN;
    const __nv_bfloat16* Blb = Blo + (size_t)bz * CC * NN;

    float acc[2][8][4];
#pragma unroll
    for (int mt = 0; mt < 2; mt++)
#pragma unroll
        for (int nt = 0; nt < 8; nt++)
#pragma unroll
            for (int i = 0; i < 4; i++) acc[mt][nt][i] = 0.f;

    int a_row0 = (tid * 2) >> 2, a_kc0 = (tid * 2) & 3;
    int a_row1 = (tid * 2 + 1) >> 2, a_kc1 = (tid * 2 + 1) & 3;
    int b_row0 = (tid * 2) >> 4, b_nc0 = (tid * 2) & 15;
    int b_row1 = (tid * 2 + 1) >> 4, b_nc1 = (tid * 2 + 1) & 15;

    auto issue_load = [&](int ck) {
        if (ck < NCHUNK) {
            int kb = ck * 32;
            uint32_t st = sb + (uint32_t)(ck % STAGES) * STAGE_BYTES;
            cp_async16(st + ST_AH + a_row0 * A_STRIDE + a_kc0 * 16,
                       Ahm + (size_t)a_row0 * CC + kb + a_kc0 * 8);
            cp_async16(st + ST_AH + a_row1 * A_STRIDE + a_kc1 * 16,
                       Ahm + (size_t)a_row1 * CC + kb + a_kc1 * 8);
            cp_async16(st + ST_AL + a_row0 * A_STRIDE + a_kc0 * 16,
                       Alm + (size_t)a_row0 * CC + kb + a_kc0 * 8);
            cp_async16(st + ST_AL + a_row1 * A_STRIDE + a_kc1 * 16,
                       Alm + (size_t)a_row1 * CC + kb + a_kc1 * 8);
            cp_async16(st + ST_BH + b_row0 * B_STRIDE + b_nc0 * 16,
                       Bhb + (size_t)(kb + b_row0) * NN + n0 + b_nc0 * 8);
            cp_async16(st + ST_BH + b_row1 * B_STRIDE + b_nc1 * 16,
                       Bhb + (size_t)(kb + b_row1) * NN + n0 + b_nc1 * 8);
            cp_async16(st + ST_BL + b_row0 * B_STRIDE + b_nc0 * 16,
                       Blb + (size_t)(kb + b_row0) * NN + n0 + b_nc0 * 8);
            cp_async16(st + ST_BL + b_row1 * B_STRIDE + b_nc1 * 16,
                       Blb + (size_t)(kb + b_row1) * NN + n0 + b_nc1 * 8);
        }
        asm volatile("cp.async.commit_group;" ::: "memory");
    };

    issue_load(0);
    issue_load(1);

    int li = lane >> 3, lr = lane & 7;

    for (int ck = 0; ck < NCHUNK; ck++) {
        asm volatile("cp.async.wait_group 1;" ::: "memory");
        __syncthreads();
        issue_load(ck + 2);

        uint32_t st = sb + (uint32_t)(ck % STAGES) * STAGE_BYTES;
#pragma unroll
        for (int ks = 0; ks < 2; ks++) {
            uint32_t ah[2][4], al[2][4];
#pragma unroll
            for (int mt = 0; mt < 2; mt++) {
                uint32_t arow = (uint32_t)(wm + mt * 16 + (li & 1) * 8 + lr) * A_STRIDE
                              + (uint32_t)(ks * 32 + (li >> 1) * 16);
                ldsm_x4(ah[mt], st + ST_AH + arow);
                ldsm_x4(al[mt], st + ST_AL + arow);
            }
#pragma unroll
            for (int j = 0; j < 4; j++) {
                uint32_t boff = (uint32_t)(ks * 16 + (li & 1) * 8 + lr) * B_STRIDE
                              + (uint32_t)(wn + j * 16 + (li >> 1) * 8) * 2;
                uint32_t th[4], tl[4];
                ldsm_x4_t(th, st + ST_BH + boff);
                ldsm_x4_t(tl, st + ST_BL + boff);
#pragma unroll
                for (int mt = 0; mt < 2; mt++) {
                    mma_bf16(acc[mt][2 * j],     ah[mt], th[0], th[1]);
                    mma_bf16(acc[mt][2 * j],     ah[mt], tl[0], tl[1]);
                    mma_bf16(acc[mt][2 * j],     al[mt], th[0], th[1]);
                    mma_bf16(acc[mt][2 * j + 1], ah[mt], th[2], th[3]);
                    mma_bf16(acc[mt][2 * j + 1], ah[mt], tl[2], tl[3]);
                    mma_bf16(acc[mt][2 * j + 1], al[mt], th[2], th[3]);
                }
            }
        }
    }

    __syncthreads();
    int g = lane >> 2, tg = lane & 3;
#pragma unroll
    for (int mt = 0; mt < 2; mt++) {
        int m = mbase + wm + mt * 16 + g;
        float bv0 = bias[m], bv1 = bias[m + 8];
        float* po0 = out + ((size_t)bz * M + m) * NN + n0 + wn + tg * 2;
        float* po1 = po0 + 8 * (size_t)NN;
#pragma unroll
        for (int nt = 0; nt < 8; nt++) {
            *(float2*)(po0 + nt * 8) = make_float2(acc[mt][nt][0] + bv0, acc[mt][nt][1] + bv0);
            *(float2*)(po1 + nt * 8) = make_float2(acc[mt][nt][2] + bv1, acc[mt][nt][3] + bv1);
        }
    }
}

// ---------------- single-pass focusing transform (q and k), 32 pixels/block ----------------
#define FOC_PIX 32
#define FOC_STR 33
#define FOC_SMEM (256 * FOC_STR * 4 + 256 * 4 + 256 * 4 + 256 * 4 + FOC_PIX * 4)
__global__ __launch_bounds__(256)
void focus_kernel() {
    extern __shared__ char fsm[];
    float* tile = (float*)fsm;                            // 256 x 33
    float* sinv = (float*)(fsm + 256 * FOC_STR * 4);      // 256
    float* sp2  = sinv + 256;                             // 8 x 32
    float* sp6  = sp2 + 256;                              // 8 x 32
    float* sf   = sp6 + 256;                              // 32
    int tid = threadIdx.x;
    int part = blockIdx.y, b = blockIdx.z;
    int n0 = blockIdx.x * FOC_PIX;
    sinv[tid] = g_invscale[tid];
    float* base = g_qkv + ((size_t)b * M_QKV + part * CC) * NN + n0;
    int j = tid & 31, ci = tid >> 5;    // ci 0..7
    __syncthreads();
#pragma unroll 8
    for (int i = 0; i < 32; i++) {
        int c = i * 8 + ci;
        float v = base[(size_t)c * NN + j];
        v = fmaxf(v, 0.f) + 1e-6f;
        tile[c * FOC_STR + j] = v * sinv[c];
    }
    __syncthreads();
    float s2 = 0.f, s6 = 0.f;
#pragma unroll 8
    for (int c = ci * 32; c < ci * 32 + 32; c++) {
        float v = tile[c * FOC_STR + j];
        float v2 = v * v, v3 = v2 * v;
        s2 += v2; s6 += v3 * v3;
        tile[c * FOC_STR + j] = v3;
    }
    sp2[ci * 32 + j] = s2;
    sp6[ci * 32 + j] = s6;
    __syncthreads();
    if (tid < 32) {
        float t2 = 0.f, t6 = 0.f;
#pragma unroll
        for (int gq = 0; gq < 8; gq++) { t2 += sp2[gq * 32 + tid]; t6 += sp6[gq * 32 + tid]; }
        sf[tid] = sqrtf(t2 / t6);
    }
    __syncthreads();
    float f = sf[j];
#pragma unroll 8
    for (int i = 0; i < 32; i++) {
        int c = i * 8 + ci;
        base[(size_t)c * NN + j] = tile[c * FOC_STR + j] * f;
    }
}

// ---------------- per-head kv_state partials: j-major smem, float4 inner loads ----------------
#define CHUNK 128
#define JSTR 36
__global__ __launch_bounds__(256)
void kvstate_kernel() {
    int bh = blockIdx.x, seg = blockIdx.y;
    int b = bh >> 3, h = bh & 7;
    const float* kbase = g_qkv + ((size_t)b * M_QKV + CC + h * HD) * NN;
    const float* vbase = g_qkv + ((size_t)b * M_QKV + 2 * CC + h * HD) * NN;
    __shared__ __align__(16) float sk[CHUNK * JSTR];
    __shared__ __align__(16) float sv[CHUNK * JSTR];
    int tid = threadIdx.x;
    int c = tid >> 3, d4 = (tid & 7) * 4;
    int lc = tid >> 3, lj4 = (tid & 7) * 4;
    float acc[4] = {0, 0, 0, 0};
    float ks = 0.f;
    int j_begin = seg * (NN / SEGS);

    for (int j0 = j_begin; j0 < j_begin + NN / SEGS; j0 += CHUNK) {
#pragma unroll
        for (int jj = 0; jj < CHUNK; jj += 32) {
            float4 k4 = *(const float4*)(kbase + (size_t)lc * NN + j0 + jj + lj4);
            float4 v4 = *(const float4*)(vbase + (size_t)lc * NN + j0 + jj + lj4);
            sk[(jj + lj4 + 0) * JSTR + lc] = k4.x;
            sk[(jj + lj4 + 1) * JSTR + lc] = k4.y;
            sk[(jj + lj4 + 2) * JSTR + lc] = k4.z;
            sk[(jj + lj4 + 3) * JSTR + lc] = k4.w;
            sv[(jj + lj4 + 0) * JSTR + lc] = v4.x;
            sv[(jj + lj4 + 1) * JSTR + lc] = v4.y;
            sv[(jj + lj4 + 2) * JSTR + lc] = v4.z;
            sv[(jj + lj4 + 3) * JSTR + lc] = v4.w;
        }
        __syncthreads();
#pragma unroll 4
        for (int j = 0; j < CHUNK; j++) {
            float kc = sk[j * JSTR + c];
            ks += kc;
            float4 v = *(const float4*)(sv + j * JSTR + d4);
            acc[0] += kc * v.x;
            acc[1] += kc * v.y;
            acc[2] += kc * v.z;
            acc[3] += kc * v.w;
        }
        __syncthreads();
    }
    float* kvs = g_kvp + ((size_t)seg * BB * NH + bh) * HD * HD;
#pragma unroll
    for (int i = 0; i < 4; i++) kvs[c * HD + d4 + i] = acc[i];
    if ((tid & 7) == 0) g_ksp[((size_t)seg * BB * NH + bh) * HD + c] = ks;
}

// ---------------- fused depthwise conv + attention output -> bf16 hi/lo mid ----------------
__global__ __launch_bounds__(256)
void conv_attn_kernel(const float* __restrict__ dwc_w, const float* __restrict__ dwc_b) {
    __shared__ float skvs[HD * HD];
    __shared__ float sks[HD];
    __shared__ float tile[20][21];
    __shared__ float wloc[25];
    int bh = blockIdx.y;
    int b = bh >> 3, h = bh & 7;
    int ty0 = (blockIdx.x >> 2) * 16;
    int tx0 = (blockIdx.x & 3) * 16;
    int tid = threadIdx.x, lx = tid & 15, ly = tid >> 4;
    int gy = ty0 + ly, gx = tx0 + lx;
    int n = gy * WW + gx;

    for (int i = tid; i < HD * HD; i += 256) {
        float s = 0.f;
#pragma unroll
        for (int seg = 0; seg < SEGS; seg++)
            s += g_kvp[((size_t)seg * BB * NH + bh) * HD * HD + i];
        skvs[i] = s;
    }
    if (tid < HD) {
        float s = 0.f;
#pragma unroll
        for (int seg = 0; seg < SEGS; seg++)
            s += g_ksp[((size_t)seg * BB * NH + bh) * HD + tid];
        sks[tid] = s;
    }

    float acc[HD];
    for (int d = 0; d < HD; d++) {
        const float* vrow = g_qkv + ((size_t)b * M_QKV + 2 * CC + h * HD + d) * NN;
        __syncthreads();
        if (tid < 25) wloc[tid] = dwc_w[d * 25 + tid];
        for (int i = tid; i < 400; i += 256) {
            int ry = i / 20, rx = i % 20;
            int sy = ty0 - 2 + ry, sx = tx0 - 2 + rx;
            float v = 0.f;
            if (sy >= 0 && sy < HH && sx >= 0 && sx < WW) v = vrow[sy * WW + sx];
            tile[ry][rx] = v;
        }
        __syncthreads();
        float a = dwc_b[d];
#pragma unroll
        for (int ky = 0; ky < 5; ky++)
#pragma unroll
            for (int kx = 0; kx < 5; kx++)
                a += tile[ly + ky][lx + kx] * wloc[ky * 5 + kx];
        acc[d] = a;
    }
    __syncthreads();

    const float* qbase = g_qkv + ((size_t)b * M_QKV + h * HD) * NN + n;
    float a2[HD];
#pragma unroll
    for (int d = 0; d < HD; d++) a2[d] = 0.f;
    float zacc = 0.f;
#pragma unroll
    for (int c = 0; c < HD; c++) {
        float qv = qbase[(size_t)c * NN];
        zacc += qv * sks[c];
#pragma unroll
        for (int d = 0; d < HD; d++) a2[d] += qv * skvs[c * HD + d];
    }
    float z = 1.0f / (zacc + 1e-6f);
    __nv_bfloat16* mh = (__nv_bfloat16*)g_mhi4;
    __nv_bfloat16* ml = (__nv_bfloat16*)g_mlo4;
#pragma unroll
    for (int d = 0; d < HD; d++) {
        size_t off = ((size_t)b * CC + h * HD + d) * NN + n;
        float v = acc[d] + a2[d] * z;
        __nv_bfloat16 hh = __float2bfloat16(v);
        mh[off] = hh;
        ml[off] = __float2bfloat16(v - __bfloat162float(hh));
    }
}

// ---------------- launch ----------------
extern "C" void kernel_launch(void* const* d_in, const int* in_sizes, int n_in,
                              void* d_out, int out_size) {
    const float* x           = (const float*)d_in[0];
    const float* Wq          = (const float*)d_in[1];
    const float* bq          = (const float*)d_in[2];
    const float* Wkv         = (const float*)d_in[3];
    const float* bkv         = (const float*)d_in[4];
    const float* Wproj       = (const float*)d_in[5];
    const float* bproj       = (const float*)d_in[6];
    const float* dwc_w       = (const float*)d_in[7];
    const float* dwc_b       = (const float*)d_in[8];
    const float* scale_param = (const float*)d_in[9];
    float* out = (float*)d_out;

    float *p_qkv, *p_bcat;
    uint4 *p_whi, *p_wlo, *p_pwhi, *p_pwlo, *p_xhi, *p_xlo, *p_mhi, *p_mlo;
    cudaGetSymbolAddress((void**)&p_qkv,  g_qkv);
    cudaGetSymbolAddress((void**)&p_bcat, g_bcat);
    cudaGetSymbolAddress((void**)&p_whi,  g_whi4);
    cudaGetSymbolAddress((void**)&p_wlo,  g_wlo4);
    cudaGetSymbolAddress((void**)&p_pwhi, g_pwhi4);
    cudaGetSymbolAddress((void**)&p_pwlo, g_pwlo4);
    cudaGetSymbolAddress((void**)&p_xhi,  g_xhi4);
    cudaGetSymbolAddress((void**)&p_xlo,  g_xlo4);
    cudaGetSymbolAddress((void**)&p_mhi,  g_mhi4);
    cudaGetSymbolAddress((void**)&p_mlo,  g_mlo4);

    cudaFuncSetAttribute(gemm_mma_kernel, cudaFuncAttributeMaxDynamicSharedMemorySize, SM_GEMM);
    cudaFuncSetAttribute(focus_kernel, cudaFuncAttributeMaxDynamicSharedMemorySize, FOC_SMEM);

    prep_kernel<<<M_QKV, CC>>>(Wq, bq, Wkv, bkv, Wproj, scale_param);

    int n4 = BB * CC * NN / 4;
    split_kernel<<<(n4 + 255) / 256, 256>>>((const float4*)x,
                                            (__nv_bfloat16*)p_xhi, (__nv_bfloat16*)p_xlo, n4);

    // QKV projection: 768x256 @ 256x4096 per batch
    gemm_mma_kernel<<<dim3(NN / 128, M_QKV / 128, BB), 256, SM_GEMM>>>(
        (const __nv_bfloat16*)p_whi, (const __nv_bfloat16*)p_wlo,
        (const __nv_bfloat16*)p_xhi, (const __nv_bfloat16*)p_xlo,
        p_bcat, p_qkv, M_QKV);

    focus_kernel<<<dim3(NN / FOC_PIX, 2, BB), 256, FOC_SMEM>>>();

    kvstate_kernel<<<dim3(BB * NH, SEGS), 256>>>();

    conv_attn_kernel<<<dim3(16, BB * NH), 256>>>(dwc_w, dwc_b);

    // Output projection: 256x256 @ 256x4096 per batch -> d_out
    gemm_mma_kernel<<<dim3(NN / 128, CC / 128, BB), 256, SM_GEMM>>>(
        (const __nv_bfloat16*)p_pwhi, (const __nv_bfloat16*)p_pwlo,
        (const __nv_bfloat16*)p_mhi, (const __nv_bfloat16*)p_mlo,
        bproj, out, CC);
}